// round 3
// baseline (speedup 1.0000x reference)
#include <cuda_runtime.h>

// LIF: per lane n, for t in 0..3:
//   v = (v + x[t][n]) - v*0.5         (tau=2, v_reset=0, decay_input=False)
//   s = (v >= 1.0f)
//   out[t][n] = s; v = s ? 0 : v
// Lanes independent -> pure streaming, vectorized float4.

__global__ void __launch_bounds__(256)
lif_kernel(const float4* __restrict__ x, float4* __restrict__ out, int n4) {
    int i = blockIdx.x * blockDim.x + threadIdx.x;
    if (i >= n4) return;

    float vx = 0.f, vy = 0.f, vz = 0.f, vw = 0.f;

#pragma unroll
    for (int t = 0; t < 4; t++) {
        float4 xt = x[(size_t)t * n4 + i];

        // exact reference order: v = (v + x) - v*0.5, no FMA contraction
        float nvx = __fadd_rn(__fadd_rn(vx, xt.x), -__fmul_rn(vx, 0.5f));
        float nvy = __fadd_rn(__fadd_rn(vy, xt.y), -__fmul_rn(vy, 0.5f));
        float nvz = __fadd_rn(__fadd_rn(vz, xt.z), -__fmul_rn(vz, 0.5f));
        float nvw = __fadd_rn(__fadd_rn(vw, xt.w), -__fmul_rn(vw, 0.5f));

        float4 s;
        s.x = (nvx >= 1.0f) ? 1.0f : 0.0f;
        s.y = (nvy >= 1.0f) ? 1.0f : 0.0f;
        s.z = (nvz >= 1.0f) ? 1.0f : 0.0f;
        s.w = (nvw >= 1.0f) ? 1.0f : 0.0f;

        out[(size_t)t * n4 + i] = s;

        vx = (s.x != 0.0f) ? 0.0f : nvx;
        vy = (s.y != 0.0f) ? 0.0f : nvy;
        vz = (s.z != 0.0f) ? 0.0f : nvz;
        vw = (s.w != 0.0f) ? 0.0f : nvw;
    }
}

extern "C" void kernel_launch(void* const* d_in, const int* in_sizes, int n_in,
                              void* d_out, int out_size) {
    const float* x = (const float*)d_in[0];
    float* out = (float*)d_out;

    const int T = 4;
    int n_total = in_sizes[0];          // 4 * 64 * 262144 = 67,108,864
    int n_per_step = n_total / T;       // 16,777,216
    int n4 = n_per_step / 4;            // 4,194,304 float4 lanes

    int threads = 256;
    int blocks = (n4 + threads - 1) / threads;
    lif_kernel<<<blocks, threads>>>((const float4*)x, (float4*)out, n4);
}